// round 15
// baseline (speedup 1.0000x reference)
#include <cuda_runtime.h>
#include <cuda_fp16.h>
#include <cuda_bf16.h>
#include <cstdint>
#include <cmath>

// ---------------- problem constants ----------------
#define LL 2
#define HH 24
#define KVH 8
#define GG 3
#define DD 128
#define ROT 96
#define HALF 48
#define HID 3072
#define FF 8192
#define VV 32000
#define SS 1024
#define QP (HH*DD)          // 3072
#define KP (KVH*DD)         // 1024
#define QKV_O (QP + 2*KP)   // 5120
#define EPS 1e-6f
__device__ __constant__ float SCALE_C = 0.29730177875068026f;

// pair-index permutation within 16-pair (=32 fp16) blocks
#define PERMP(j) (((j) & ~15) | (((j) & 3) << 2) | (((j) >> 2) & 3))
// fp16-element permutation (pairs permuted, low/high kept)
#define PERMH(e) ((PERMP((e) >> 1) << 1) | ((e) & 1))

// ---------------- scratch (float-unit offsets; fp16 buffers use half) -------
#define OFF_H      0ull
#define OFF_HN     (OFF_H   + (size_t)SS*HID)
#define OFF_QKV    (OFF_HN  + (size_t)SS*HID)
#define OFF_Q      (OFF_QKV + (size_t)SS*QKV_O)
#define OFF_SC     (OFF_Q   + (size_t)HH*SS*DD)
#define OFF_PB     (OFF_SC  + (size_t)HH*SS*SS)
#define OFF_AO     (OFF_PB  + (size_t)HH*SS*SS)
#define OFF_ACT    (OFF_AO  + (size_t)SS*HID)
#define OFF_KT     (OFF_ACT + (size_t)SS*FF)
#define OFF_VT     (OFF_KT  + (size_t)KVH*SS*DD)
#define OFF_HL     (OFF_VT  + (size_t)KVH*DD*SS)
#define OFF_LG     (OFF_HL  + (size_t)HID)
#define OFF_FLAG   (OFF_LG  + (size_t)VV)
#define OFF_WQKV   (OFF_FLAG + 16)
#define OFF_WO     (OFF_WQKV + (size_t)LL*QKV_O*HID)
#define OFF_WGU    (OFF_WO   + (size_t)LL*HID*QP)
#define OFF_WDW    (OFF_WGU  + (size_t)LL*2*FF*HID)
#define SCRATCH_TOTAL (OFF_WDW + (size_t)LL*HID*FF)

__device__ float g_scratch[SCRATCH_TOTAL];

// output layout (4-byte elements)
#define OUT_KEYS   0ull
#define OUT_VALS   ((size_t)LL*KVH*DD*SS)
#define OUT_KVLEN  (2ull*LL*KVH*DD*SS)
#define OUT_TOKEN  (OUT_KVLEN + 1)

// ---------------- helpers ----------------
__device__ __forceinline__ unsigned pack_h2(float lo, float hi) {
    __half2 h = __floats2half2_rn(lo, hi);   // .x (low) = lo
    return *(unsigned*)&h;
}
__device__ __forceinline__ void mma_f16(float* d, const unsigned* a, const unsigned* b) {
    asm("mma.sync.aligned.m16n8k16.row.col.f32.f16.f16.f32 "
        "{%0,%1,%2,%3}, {%4,%5,%6,%7}, {%8,%9}, {%0,%1,%2,%3};"
        : "+f"(d[0]), "+f"(d[1]), "+f"(d[2]), "+f"(d[3])
        : "r"(a[0]), "r"(a[1]), "r"(a[2]), "r"(a[3]),
          "r"(b[0]), "r"(b[1]));
}
__device__ __forceinline__ void cp_async16(void* dst, const void* src) {
    unsigned d = (unsigned)__cvta_generic_to_shared(dst);
    asm volatile("cp.async.cg.shared.global [%0], [%1], 16;\n" :: "r"(d), "l"(src));
}
__device__ __forceinline__ void cp_commit() { asm volatile("cp.async.commit_group;\n"); }
__device__ __forceinline__ void cp_wait1()  { asm volatile("cp.async.wait_group 1;\n"); }
__device__ __forceinline__ void cp_wait0()  { asm volatile("cp.async.wait_group 0;\n"); }

// ---------------- dtype probe for embed_q ----------------
__global__ void detect_dtype_kernel(const unsigned int* __restrict__ w,
                                    int* __restrict__ mode)
{
    bool all_small = true, all_f32 = true, all_bf16 = true;
    for (int i = 0; i < 64; i++) {
        unsigned int x = w[i];
        if (x > 255u) all_small = false;
        float f = __uint_as_float(x);
        if (!(f >= 0.f && f <= 255.f && f == rintf(f))) all_f32 = false;
        float f0 = __uint_as_float(x << 16);
        float f1 = __uint_as_float(x & 0xFFFF0000u);
        if (!(f0 >= 0.f && f0 <= 255.f && f0 == rintf(f0) &&
              f1 >= 0.f && f1 <= 255.f && f1 == rintf(f1))) all_bf16 = false;
    }
    *mode = all_small ? 1 : (all_f32 ? 2 : (all_bf16 ? 3 : 0));
}

// ---------------- embed ----------------
__global__ void embed_kernel(const int* __restrict__ ids,
                             const void* __restrict__ eq,
                             const float* __restrict__ escale,
                             const float* __restrict__ ezero,
                             const int* __restrict__ modep,
                             float* __restrict__ h)
{
    int s = blockIdx.x;
    int id = ids[s];
    float sc = escale[id], z = ezero[id];
    float* out = h + (size_t)s * HID;
    int mode = *modep;
    if (mode == 1) {
        const int* row = (const int*)eq + (size_t)id * HID;
        for (int j = threadIdx.x; j < HID; j += blockDim.x)
            out[j] = (float)row[j] * sc + z;
    } else if (mode == 2) {
        const float* row = (const float*)eq + (size_t)id * HID;
        for (int j = threadIdx.x; j < HID; j += blockDim.x)
            out[j] = row[j] * sc + z;
    } else if (mode == 3) {
        const unsigned short* row = (const unsigned short*)eq + (size_t)id * HID;
        for (int j = threadIdx.x; j < HID; j += blockDim.x)
            out[j] = __uint_as_float(((unsigned int)row[j]) << 16) * sc + z;
    } else {
        const unsigned char* row = (const unsigned char*)eq + (size_t)id * HID;
        for (int j = threadIdx.x; j < HID; j += blockDim.x)
            out[j] = (float)row[j] * sc + z;
    }
}

// ---------------- weight convert: fp32 -> fp16 pairs (u32), pair-permuted ---
__global__ void convperm_h_kernel(const float* __restrict__ src,
                                  unsigned* __restrict__ dst, long n)
{
    long i4 = ((long)blockIdx.x * blockDim.x + threadIdx.x) * 4;
    if (i4 >= n) return;
    float4 v = *(const float4*)(src + i4);
    long j0 = i4 >> 1;           // even pair index
    long blk = j0 & ~15L;
    int lo0 = (int)(j0 & 15), lo1 = lo0 + 1;
    dst[blk + (((lo0 & 3) << 2) | ((lo0 >> 2) & 3))] = pack_h2(v.x, v.y);
    dst[blk + (((lo1 & 3) << 2) | ((lo1 >> 2) & 3))] = pack_h2(v.z, v.w);
}

// gate_up variant: interleave rows (dst row 2f = gate f, 2f+1 = up f)
__global__ void convperm_gu_kernel(const float* __restrict__ src,
                                   unsigned* __restrict__ dst, long n)
{
    long i4 = ((long)blockIdx.x * blockDim.x + threadIdx.x) * 4;
    if (i4 >= n) return;
    long rowd = i4 / HID;
    int  l = (int)(rowd / (2 * FF));
    int  j = (int)(rowd % (2 * FF));
    int  srcj = (j & 1) ? (FF + (j >> 1)) : (j >> 1);
    long si = ((long)l * 2 * FF + srcj) * HID + (i4 % HID);
    float4 v = *(const float4*)(src + si);
    long j0 = i4 >> 1;
    long blk = j0 & ~15L;
    int lo0 = (int)(j0 & 15), lo1 = lo0 + 1;
    dst[blk + (((lo0 & 3) << 2) | ((lo0 >> 2) & 3))] = pack_h2(v.x, v.y);
    dst[blk + (((lo1 & 3) << 2) | ((lo1 >> 2) & 3))] = pack_h2(v.z, v.w);
}

// ---------------- RMSNorm (f32 out, or fp16-permuted out) ----------------
template<bool H16>
__global__ void rmsnorm_kernel(const float* __restrict__ in,
                               const float* __restrict__ w,
                               void* __restrict__ outv, int n)
{
    __shared__ float red[256];
    int row = blockIdx.x;
    const float* x = in + (size_t)row * n;
    float s = 0.f;
    for (int i = threadIdx.x; i < n; i += 256) { float v = x[i]; s += v * v; }
    red[threadIdx.x] = s; __syncthreads();
    for (int st = 128; st > 0; st >>= 1) {
        if (threadIdx.x < st) red[threadIdx.x] += red[threadIdx.x + st];
        __syncthreads();
    }
    float inv = rsqrtf(red[0] / (float)n + EPS);
    if (H16) {
        __half* y = (__half*)outv + (size_t)row * n;
        for (int i = threadIdx.x; i < n; i += 256)
            y[PERMH(i)] = __float2half_rn(w[i] * x[i] * inv);
    } else {
        float* y = (float*)outv + (size_t)row * n;
        for (int i = threadIdx.x; i < n; i += 256)
            y[i] = w[i] * x[i] * inv;
    }
}

// ---------------- fp16 GEMM, batched, K-step 64, 3-stage, 8 warps ----------
// A [M,K] fp16 pair-permuted (u32 view), B [N,K] same (TRANSB form).
// CTA 128x128, 256 thr, 8 warps (2m x 4n), warp tile 64x32.
// Stage: A/B = [2 blk][128 row][16 u32]; 32KB/stage, 3 stages (96KB dyn smem).
// OUTMODE: 0 = store f32, 1 = accumulate f32, 2 = store fp16-permuted,
//          3 = fused silu(gate)*up -> fp16-permuted (gate/up interleaved cols)
// cmode: 0 none; 1 = causal K-limit (K_eff = m0+128); 2 = causal tile skip.
template<int OUTMODE>
__global__ __launch_bounds__(256, 2) void hgemm_kernel(
    const unsigned* __restrict__ A, int lda, long sA,
    const unsigned* __restrict__ B, int ldb, long sB, int gdivB,
    void* __restrict__ Cv, int ldc, long sC,
    int K, const int* __restrict__ maskp, int cmode)
{
    extern __shared__ __align__(16) unsigned smem[];   // 3 * 8192 u32

    int bz = blockIdx.z;
    A += (long)bz * sA;
    B += (long)(bz / gdivB) * sB;
    int m0 = blockIdx.y * 128, n0 = blockIdx.x * 128;

    int mon = (maskp != nullptr) ? *maskp : 1;
    if (cmode == 2 && mon && n0 > m0 + 127) return;
    int Keff = K;
    if (cmode == 1 && mon) { int lim = m0 + 128; Keff = (lim < K) ? lim : K; }

    int tid = threadIdx.x;
    int wid = tid >> 5, lane = tid & 31;
    int wm = (wid >> 2) * 64;          // 2 warps in m
    int wn = (wid & 3) * 32;           // 4 warps in n
    int g = lane >> 2, tig = lane & 3;

    float acc[4][4][4];
#pragma unroll
    for (int mi = 0; mi < 4; mi++)
#pragma unroll
        for (int ni = 0; ni < 4; ni++)
#pragma unroll
            for (int r = 0; r < 4; r++) acc[mi][ni][r] = 0.f;

    int nk = Keff >> 6;   // 64 fp16 = 32 u32 per iteration

#define PREFETCH_H(s, k0u)                                                      \
    {                                                                           \
        unsigned* as = smem + (s) * 8192;                                       \
        unsigned* bs = as + 4096;                                               \
        _Pragma("unroll")                                                       \
        for (int i = 0; i < 4; i++) {                                           \
            int c = tid + i * 256;                                              \
            int r = c >> 3, sub = c & 7;                                        \
            int blk = sub >> 2, cf = (sub & 3) * 4;                             \
            cp_async16(as + blk * 2048 + r * 16 + cf,                           \
                       A + (long)(m0 + r) * lda + (k0u) + blk * 16 + cf);       \
            cp_async16(bs + blk * 2048 + r * 16 + cf,                           \
                       B + (long)(n0 + r) * ldb + (k0u) + blk * 16 + cf);       \
        }                                                                       \
        cp_commit();                                                            \
    }

    PREFETCH_H(0, 0);
    if (nk > 1) PREFETCH_H(1, 32);

    int bufc = 0, bufp = 2;
    for (int it = 0; it < nk; it++) {
        if (it + 1 < nk) cp_wait1(); else cp_wait0();
        __syncthreads();
        if (it + 2 < nk) {
            PREFETCH_H(bufp, (it + 2) * 32);
            bufp = (bufp == 2) ? 0 : bufp + 1;
        }

        const unsigned* as = smem + bufc * 8192;
        const unsigned* bs = as + 4096;
        bufc = (bufc == 2) ? 0 : bufc + 1;

#pragma unroll
        for (int blk = 0; blk < 2; blk++) {
            const unsigned* ab = as + blk * 2048;
            const unsigned* bb = bs + blk * 2048;

            uint4 qb[4];
#pragma unroll
            for (int ni = 0; ni < 4; ni++)
                qb[ni] = *(const uint4*)&bb[(wn + ni * 8 + g) * 16 + tig * 4];

#pragma unroll
            for (int mi = 0; mi < 4; mi++) {
                int mr = wm + mi * 16 + g;
                uint4 qg = *(const uint4*)&ab[mr * 16 + tig * 4];
                uint4 qh = *(const uint4*)&ab[(mr + 8) * 16 + tig * 4];
                unsigned a0[4] = {qg.x, qh.x, qg.y, qh.y};
                unsigned a1[4] = {qg.z, qh.z, qg.w, qh.w};
#pragma unroll
                for (int ni = 0; ni < 4; ni++) {
                    unsigned b0[2] = {qb[ni].x, qb[ni].y};
                    mma_f16(acc[mi][ni], a0, b0);
                }
#pragma unroll
                for (int ni = 0; ni < 4; ni++) {
                    unsigned b1[2] = {qb[ni].z, qb[ni].w};
                    mma_f16(acc[mi][ni], a1, b1);
                }
            }
        }
    }

#pragma unroll
    for (int mi = 0; mi < 4; mi++) {
        int row = m0 + wm + mi * 16 + g;
#pragma unroll
        for (int ni = 0; ni < 4; ni++) {
            int col = n0 + wn + ni * 8 + 2 * tig;
            if (OUTMODE == 2) {
                __half* Ch = (__half*)Cv + (long)bz * sC;
                Ch[(long)row * ldc + PERMH(col)]     = __float2half_rn(acc[mi][ni][0]);
                Ch[(long)row * ldc + PERMH(col + 1)] = __float2half_rn(acc[mi][ni][1]);
                Ch[(long)(row + 8) * ldc + PERMH(col)]     = __float2half_rn(acc[mi][ni][2]);
                Ch[(long)(row + 8) * ldc + PERMH(col + 1)] = __float2half_rn(acc[mi][ni][3]);
            } else if (OUTMODE == 3) {
                __half* Ch = (__half*)Cv;
                int f0 = col >> 1;        // col even: (gate, up) pair
                float g0 = acc[mi][ni][0], u0 = acc[mi][ni][1];
                float g1 = acc[mi][ni][2], u1 = acc[mi][ni][3];
                Ch[(long)row * ldc + PERMH(f0)] =
                    __float2half_rn((g0 / (1.f + expf(-g0))) * u0);
                Ch[(long)(row + 8) * ldc + PERMH(f0)] =
                    __float2half_rn((g1 / (1.f + expf(-g1))) * u1);
            } else {
                float* C = (float*)Cv + (long)bz * sC;
                float2* p0 = (float2*)(C + (long)row * ldc + col);
                float2* p1 = (float2*)(C + (long)(row + 8) * ldc + col);
                if (OUTMODE == 1) {
                    float2 o0 = *p0, o1 = *p1;
                    o0.x += acc[mi][ni][0]; o0.y += acc[mi][ni][1];
                    o1.x += acc[mi][ni][2]; o1.y += acc[mi][ni][3];
                    *p0 = o0; *p1 = o1;
                } else {
                    *p0 = make_float2(acc[mi][ni][0], acc[mi][ni][1]);
                    *p1 = make_float2(acc[mi][ni][2], acc[mi][ni][3]);
                }
            }
        }
    }
}
#undef PREFETCH_H

#define HSMEM (3 * 8192 * 4)

// ---------------- split qkv + rope + scale ----------------
__global__ void rope_split_kernel(const float* __restrict__ qkv,
                                  const float* __restrict__ cosE,
                                  const float* __restrict__ sinE,
                                  __half* __restrict__ q_h,
                                  float* __restrict__ keys,     // [KV][D][S]
                                  float* __restrict__ vals,     // [KV][S][D]
                                  __half* __restrict__ kT_h,
                                  __half* __restrict__ vT_h)
{
    long idx = (long)blockIdx.x * blockDim.x + threadIdx.x;
    if (idx >= (long)SS * QKV_O) return;
    int s = (int)(idx / QKV_O);
    int c = (int)(idx % QKV_O);
    float v = qkv[idx];
    float scale = SCALE_C;
    if (c < QP) {
        int hh = c / DD, d = c % DD;
        float val = v * scale;
        if (d < ROT) {
            int pd = (d < HALF) ? d + HALF : d - HALF;
            float partner = qkv[(long)s * QKV_O + hh * DD + pd] * scale;
            float r = (d < HALF) ? -partner : partner;
            val = val * cosE[s * ROT + d] + r * sinE[s * ROT + d];
        }
        q_h[((size_t)hh * SS + s) * DD + PERMH(d)] = __float2half_rn(val);
    } else if (c < QP + KP) {
        int kc = c - QP;
        int kv = kc / DD, d = kc % DD;
        float val = v * scale;
        if (d < ROT) {
            int pd = (d < HALF) ? d + HALF : d - HALF;
            float partner = qkv[(long)s * QKV_O + QP + kv * DD + pd] * scale;
            float r = (d < HALF) ? -partner : partner;
            val = val * cosE[s * ROT + d] + r * sinE[s * ROT + d];
        }
        keys[((size_t)kv * DD + d) * SS + s] = val;
        kT_h[((size_t)kv * SS + s) * DD + PERMH(d)] = __float2half_rn(val);
    } else {
        int vc = c - QP - KP;
        int kv = vc / DD, d = vc % DD;
        vals[((size_t)kv * SS + s) * DD + d] = v;
        vT_h[((size_t)kv * DD + d) * SS + PERMH(s)] = __float2half_rn(v);
    }
}

// ---------------- softmax: causal-aware; writes fp16-permuted probs ---------
__global__ void softmax_kernel(const float* __restrict__ sc,
                               __half* __restrict__ pb,
                               const int* __restrict__ maskf)
{
    __shared__ float red[256];
    int s = blockIdx.x, h = blockIdx.y;
    const float* row = sc + ((size_t)h * SS + s) * SS;
    __half* prow = pb + ((size_t)h * SS + s) * SS;
    int mflag = maskf ? *maskf : 1;
    bool cz = (mflag != 0);
    int tid = threadIdx.x;
    float vals[4]; bool act[4];
    float lmax = -3.4e38f;
#pragma unroll
    for (int i = 0; i < 4; i++) {
        int t = tid + i * 256;
        bool a = (!cz) || (t <= s);
        act[i] = a;
        float x = a ? row[t] : -3.4e38f;
        vals[i] = x;
        lmax = fmaxf(lmax, x);
    }
    red[tid] = lmax; __syncthreads();
    for (int st = 128; st > 0; st >>= 1) {
        if (tid < st) red[tid] = fmaxf(red[tid], red[tid + st]);
        __syncthreads();
    }
    float mx = red[0]; __syncthreads();
    float lsum = 0.f;
#pragma unroll
    for (int i = 0; i < 4; i++) {
        vals[i] = act[i] ? expf(vals[i] - mx) : 0.f;
        lsum += vals[i];
    }
    red[tid] = lsum; __syncthreads();
    for (int st = 128; st > 0; st >>= 1) {
        if (tid < st) red[tid] += red[tid + st];
        __syncthreads();
    }
    float inv = 1.f / red[0];
#pragma unroll
    for (int i = 0; i < 4; i++) {
        int t = tid + i * 256;
        prow[PERMH(t)] = __float2half_rn(vals[i] * inv);
    }
}

// ---------------- lm_head ----------------
__global__ void lmhead_kernel(const float* __restrict__ hl,
                              const float* __restrict__ w,
                              float* __restrict__ logits)
{
    int gtid = blockIdx.x * blockDim.x + threadIdx.x;
    int warp = gtid >> 5, lane = gtid & 31;
    if (warp >= VV) return;
    const float* wr = w + (size_t)warp * HID;
    float s = 0.f;
    for (int k = lane; k < HID; k += 32) s = fmaf(hl[k], wr[k], s);
#pragma unroll
    for (int off = 16; off > 0; off >>= 1)
        s += __shfl_down_sync(0xffffffffu, s, off);
    if (lane == 0) logits[warp] = s;
}

// ---------------- argmax + scalar outputs ----------------
__global__ void argmax_kernel(const float* __restrict__ lg, float* __restrict__ outf)
{
    __shared__ float bv[1024];
    __shared__ int   bi[1024];
    int tid = threadIdx.x;
    float best = -3.4e38f; int bidx = 0;
    for (int t = tid; t < VV; t += 1024) {
        float v = lg[t];
        if (v > best) { best = v; bidx = t; }
    }
    bv[tid] = best; bi[tid] = bidx; __syncthreads();
    for (int st = 512; st > 0; st >>= 1) {
        if (tid < st) {
            if (bv[tid + st] > bv[tid] ||
                (bv[tid + st] == bv[tid] && bi[tid + st] < bi[tid])) {
                bv[tid] = bv[tid + st]; bi[tid] = bi[tid + st];
            }
        }
        __syncthreads();
    }
    if (tid == 0) {
        outf[OUT_KVLEN] = (float)SS;
        outf[OUT_TOKEN] = (float)bi[0];
    }
}

// ---------------- launch ----------------
extern "C" void kernel_launch(void* const* d_in, const int* in_sizes, int n_in,
                              void* d_out, int out_size)
{
    int i_ids = -1, i_mask = -1, i_eq = -1, i_lm = -1, i_esc = -1, i_ez = -1;
    int i_l1 = -1, i_l2 = -1, i_qkv = -1, i_ow = -1, i_gu = -1, i_dw = -1;
    int i_nw = -1, i_cos = -1, i_sin = -1;
    for (int i = 0; i < n_in; i++) {
        switch (in_sizes[i]) {
            case 1024:      i_ids = i; break;
            case 1:         i_mask = i; break;
            case 98304000:  if (i_eq < 0) i_eq = i; else i_lm = i; break;
            case 32000:     if (i_esc < 0) i_esc = i; else i_ez = i; break;
            case 6144:      if (i_l1 < 0) i_l1 = i; else i_l2 = i; break;
            case 31457280:  i_qkv = i; break;
            case 18874368:  i_ow = i; break;
            case 100663296: i_gu = i; break;
            case 50331648:  i_dw = i; break;
            case 3072:      i_nw = i; break;
            case 98304:     if (i_cos < 0) i_cos = i; else i_sin = i; break;
            default: break;
        }
    }
    const int*   ids    = (const int*)d_in[i_ids];
    const int*   maskf  = (i_mask >= 0) ? (const int*)d_in[i_mask] : nullptr;
    const void*  eq     = d_in[i_eq];
    const float* escale = (const float*)d_in[i_esc];
    const float* ezero  = (const float*)d_in[i_ez];
    const float* ln1    = (const float*)d_in[i_l1];
    const float* qkvw   = (const float*)d_in[i_qkv];
    const float* ow     = (const float*)d_in[i_ow];
    const float* ln2    = (const float*)d_in[i_l2];
    const float* guw    = (const float*)d_in[i_gu];
    const float* dw     = (const float*)d_in[i_dw];
    const float* normw  = (const float*)d_in[i_nw];
    const float* lmw    = (const float*)d_in[i_lm];
    const float* cosE   = (const float*)d_in[i_cos];
    const float* sinE   = (const float*)d_in[i_sin];
    float* out = (float*)d_out;

    float* scr = nullptr;
    cudaGetSymbolAddress((void**)&scr, g_scratch);
    float*    hbuf   = scr + OFF_H;
    __half*   hn_h   = (__half*)(scr + OFF_HN);
    float*    qkv    = scr + OFF_QKV;
    __half*   q_h    = (__half*)(scr + OFF_Q);
    float*    scores = scr + OFF_SC;
    __half*   probs  = (__half*)(scr + OFF_PB);
    __half*   ao_h   = (__half*)(scr + OFF_AO);
    __half*   act_h  = (__half*)(scr + OFF_ACT);
    __half*   kT_h   = (__half*)(scr + OFF_KT);
    __half*   vT_h   = (__half*)(scr + OFF_VT);
    float*    hl     = scr + OFF_HL;
    float*    logits = scr + OFF_LG;
    int*      flag   = (int*)(scr + OFF_FLAG);
    unsigned* wqkv_c = (unsigned*)(scr + OFF_WQKV);
    unsigned* wo_c   = (unsigned*)(scr + OFF_WO);
    unsigned* wgu_c  = (unsigned*)(scr + OFF_WGU);
    unsigned* wdw_c  = (unsigned*)(scr + OFF_WDW);
    float*    keys   = out + OUT_KEYS;
    float*    valsb  = out + OUT_VALS;

    cudaFuncSetAttribute(hgemm_kernel<0>,
                         cudaFuncAttributeMaxDynamicSharedMemorySize, HSMEM);
    cudaFuncSetAttribute(hgemm_kernel<1>,
                         cudaFuncAttributeMaxDynamicSharedMemorySize, HSMEM);
    cudaFuncSetAttribute(hgemm_kernel<2>,
                         cudaFuncAttributeMaxDynamicSharedMemorySize, HSMEM);
    cudaFuncSetAttribute(hgemm_kernel<3>,
                         cudaFuncAttributeMaxDynamicSharedMemorySize, HSMEM);

    // ---- one-time-per-launch weight conversion (fp16 + pair-permute) ----
    {
        long n;
        n = (long)LL * QKV_O * HID;
        convperm_h_kernel<<<(unsigned)((n / 4 + 255) / 256), 256>>>(qkvw, wqkv_c, n);
        n = (long)LL * HID * QP;
        convperm_h_kernel<<<(unsigned)((n / 4 + 255) / 256), 256>>>(ow, wo_c, n);
        n = (long)LL * 2 * FF * HID;
        convperm_gu_kernel<<<(unsigned)((n / 4 + 255) / 256), 256>>>(guw, wgu_c, n);
        n = (long)LL * HID * FF;
        convperm_h_kernel<<<(unsigned)((n / 4 + 255) / 256), 256>>>(dw, wdw_c, n);
    }

    detect_dtype_kernel<<<1, 1>>>((const unsigned int*)eq, flag);
    embed_kernel<<<SS, 256>>>(ids, eq, escale, ezero, flag, hbuf);

    for (int l = 0; l < LL; l++) {
        float* lkeys = keys  + (size_t)l * KVH * DD * SS;
        float* lvals = valsb + (size_t)l * KVH * SS * DD;

        // hn = rms(h, ln1)  (fp16-permuted)
        rmsnorm_kernel<true><<<SS, 256>>>(hbuf, ln1 + (size_t)l * HID, hn_h, HID);
        // qkv = hn @ qkv_w^T
        hgemm_kernel<0><<<dim3(QKV_O / 128, SS / 128, 1), 256, HSMEM>>>(
            (const unsigned*)hn_h, HID / 2, 0,
            wqkv_c + (size_t)l * QKV_O * HID / 2, HID / 2, 0, 1,
            qkv, QKV_O, 0, HID, nullptr, 0);
        // rope + split (f32 caches + fp16 attention operands)
        rope_split_kernel<<<(SS * QKV_O) / 256, 256>>>(
            qkv, cosE, sinE, q_h, lkeys, lvals, kT_h, vT_h);
        // scores = q @ k^T (causal tile skip)
        hgemm_kernel<0><<<dim3(SS / 128, SS / 128, HH), 256, HSMEM>>>(
            (const unsigned*)q_h, DD / 2, (long)SS * DD / 2,
            (const unsigned*)kT_h, DD / 2, (long)SS * DD / 2, GG,
            scores, SS, (long)SS * SS, DD, maskf, 2);
        // softmax -> fp16-permuted probs (causal-aware)
        softmax_kernel<<<dim3(SS, HH), 256>>>(scores, probs, maskf);
        // ao = P @ v  (causal K-limit) -> fp16-permuted
        hgemm_kernel<2><<<dim3(DD / 128, SS / 128, HH), 256, HSMEM>>>(
            (const unsigned*)probs, SS / 2, (long)SS * SS / 2,
            (const unsigned*)vT_h, SS / 2, (long)DD * SS / 2, GG,
            ao_h, HID, (long)DD, SS, maskf, 1);
        // h += ao @ o_w^T
        hgemm_kernel<1><<<dim3(HID / 128, SS / 128, 1), 256, HSMEM>>>(
            (const unsigned*)ao_h, QP / 2, 0,
            wo_c + (size_t)l * HID * QP / 2, QP / 2, 0, 1,
            hbuf, HID, 0, QP, nullptr, 0);
        // hn = rms(h, ln2) (fp16-permuted)
        rmsnorm_kernel<true><<<SS, 256>>>(hbuf, ln2 + (size_t)l * HID, hn_h, HID);
        // act = silu(gate)*up fused into gate_up GEMM (interleaved weights)
        hgemm_kernel<3><<<dim3(2 * FF / 128, SS / 128, 1), 256, HSMEM>>>(
            (const unsigned*)hn_h, HID / 2, 0,
            wgu_c + (size_t)l * 2 * FF * HID / 2, HID / 2, 0, 1,
            act_h, FF, 0, HID, nullptr, 0);
        // h += act @ down_w^T
        hgemm_kernel<1><<<dim3(HID / 128, SS / 128, 1), 256, HSMEM>>>(
            (const unsigned*)act_h, FF / 2, 0,
            wdw_c + (size_t)l * HID * FF / 2, FF / 2, 0, 1,
            hbuf, HID, 0, FF, nullptr, 0);
    }

    rmsnorm_kernel<false><<<1, 256>>>(hbuf + (size_t)(SS - 1) * HID, normw, hl, HID);
    lmhead_kernel<<<(VV * 32) / 256, 256>>>(hl, lmw, logits);
    argmax_kernel<<<1, 1024>>>(logits, (float*)d_out);
}

// round 16
// speedup vs baseline: 1.0698x; 1.0698x over previous
#include <cuda_runtime.h>
#include <cuda_fp16.h>
#include <cuda_bf16.h>
#include <cstdint>
#include <cmath>

// ---------------- problem constants ----------------
#define LL 2
#define HH 24
#define KVH 8
#define GG 3
#define DD 128
#define ROT 96
#define HALF 48
#define HID 3072
#define FF 8192
#define VV 32000
#define SS 1024
#define QP (HH*DD)          // 3072
#define KP (KVH*DD)         // 1024
#define QKV_O (QP + 2*KP)   // 5120
#define EPS 1e-6f
__device__ __constant__ float SCALE_C = 0.29730177875068026f;

// pair-index permutation within 16-pair (=32 fp16) blocks
#define PERMP(j) (((j) & ~15) | (((j) & 3) << 2) | (((j) >> 2) & 3))
// fp16-element permutation (pairs permuted, low/high kept)
#define PERMH(e) ((PERMP((e) >> 1) << 1) | ((e) & 1))

// ---------------- scratch (float-unit offsets; fp16 buffers use half) -------
#define OFF_H      0ull
#define OFF_HN     (OFF_H   + (size_t)SS*HID)
#define OFF_QKV    (OFF_HN  + (size_t)SS*HID)
#define OFF_Q      (OFF_QKV + (size_t)SS*QKV_O)
#define OFF_SC     (OFF_Q   + (size_t)HH*SS*DD)
#define OFF_PB     (OFF_SC  + (size_t)HH*SS*SS)
#define OFF_AO     (OFF_PB  + (size_t)HH*SS*SS)
#define OFF_ACT    (OFF_AO  + (size_t)SS*HID)
#define OFF_KT     (OFF_ACT + (size_t)SS*FF)
#define OFF_VT     (OFF_KT  + (size_t)KVH*SS*DD)
#define OFF_HL     (OFF_VT  + (size_t)KVH*DD*SS)
#define OFF_LG     (OFF_HL  + (size_t)HID)
#define OFF_FLAG   (OFF_LG  + (size_t)VV)
#define OFF_WQKV   (OFF_FLAG + 16)
#define OFF_WO     (OFF_WQKV + (size_t)LL*QKV_O*HID)
#define OFF_WGU    (OFF_WO   + (size_t)LL*HID*QP)
#define OFF_WDW    (OFF_WGU  + (size_t)LL*2*FF*HID)
#define SCRATCH_TOTAL (OFF_WDW + (size_t)LL*HID*FF)

__device__ float g_scratch[SCRATCH_TOTAL];

// output layout (4-byte elements)
#define OUT_KEYS   0ull
#define OUT_VALS   ((size_t)LL*KVH*DD*SS)
#define OUT_KVLEN  (2ull*LL*KVH*DD*SS)
#define OUT_TOKEN  (OUT_KVLEN + 1)

// ---------------- helpers ----------------
__device__ __forceinline__ unsigned pack_h2(float lo, float hi) {
    __half2 h = __floats2half2_rn(lo, hi);   // .x (low) = lo
    return *(unsigned*)&h;
}
__device__ __forceinline__ void mma_f16(float* d, const unsigned* a, const unsigned* b) {
    asm("mma.sync.aligned.m16n8k16.row.col.f32.f16.f16.f32 "
        "{%0,%1,%2,%3}, {%4,%5,%6,%7}, {%8,%9}, {%0,%1,%2,%3};"
        : "+f"(d[0]), "+f"(d[1]), "+f"(d[2]), "+f"(d[3])
        : "r"(a[0]), "r"(a[1]), "r"(a[2]), "r"(a[3]),
          "r"(b[0]), "r"(b[1]));
}
__device__ __forceinline__ void cp_async16(void* dst, const void* src) {
    unsigned d = (unsigned)__cvta_generic_to_shared(dst);
    asm volatile("cp.async.cg.shared.global [%0], [%1], 16;\n" :: "r"(d), "l"(src));
}
__device__ __forceinline__ void cp_commit() { asm volatile("cp.async.commit_group;\n"); }
__device__ __forceinline__ void cp_wait1()  { asm volatile("cp.async.wait_group 1;\n"); }
__device__ __forceinline__ void cp_wait0()  { asm volatile("cp.async.wait_group 0;\n"); }

// ---------------- dtype probe for embed_q ----------------
__global__ void detect_dtype_kernel(const unsigned int* __restrict__ w,
                                    int* __restrict__ mode)
{
    bool all_small = true, all_f32 = true, all_bf16 = true;
    for (int i = 0; i < 64; i++) {
        unsigned int x = w[i];
        if (x > 255u) all_small = false;
        float f = __uint_as_float(x);
        if (!(f >= 0.f && f <= 255.f && f == rintf(f))) all_f32 = false;
        float f0 = __uint_as_float(x << 16);
        float f1 = __uint_as_float(x & 0xFFFF0000u);
        if (!(f0 >= 0.f && f0 <= 255.f && f0 == rintf(f0) &&
              f1 >= 0.f && f1 <= 255.f && f1 == rintf(f1))) all_bf16 = false;
    }
    *mode = all_small ? 1 : (all_f32 ? 2 : (all_bf16 ? 3 : 0));
}

// ---------------- embed ----------------
__global__ void embed_kernel(const int* __restrict__ ids,
                             const void* __restrict__ eq,
                             const float* __restrict__ escale,
                             const float* __restrict__ ezero,
                             const int* __restrict__ modep,
                             float* __restrict__ h)
{
    int s = blockIdx.x;
    int id = ids[s];
    float sc = escale[id], z = ezero[id];
    float* out = h + (size_t)s * HID;
    int mode = *modep;
    if (mode == 1) {
        const int* row = (const int*)eq + (size_t)id * HID;
        for (int j = threadIdx.x; j < HID; j += blockDim.x)
            out[j] = (float)row[j] * sc + z;
    } else if (mode == 2) {
        const float* row = (const float*)eq + (size_t)id * HID;
        for (int j = threadIdx.x; j < HID; j += blockDim.x)
            out[j] = row[j] * sc + z;
    } else if (mode == 3) {
        const unsigned short* row = (const unsigned short*)eq + (size_t)id * HID;
        for (int j = threadIdx.x; j < HID; j += blockDim.x)
            out[j] = __uint_as_float(((unsigned int)row[j]) << 16) * sc + z;
    } else {
        const unsigned char* row = (const unsigned char*)eq + (size_t)id * HID;
        for (int j = threadIdx.x; j < HID; j += blockDim.x)
            out[j] = (float)row[j] * sc + z;
    }
}

// ---------------- weight convert: fp32 -> fp16 pairs (u32), pair-permuted ---
__global__ void convperm_h_kernel(const float* __restrict__ src,
                                  unsigned* __restrict__ dst, long n)
{
    long i4 = ((long)blockIdx.x * blockDim.x + threadIdx.x) * 4;
    if (i4 >= n) return;
    float4 v = *(const float4*)(src + i4);
    long j0 = i4 >> 1;           // even pair index
    long blk = j0 & ~15L;
    int lo0 = (int)(j0 & 15), lo1 = lo0 + 1;
    dst[blk + (((lo0 & 3) << 2) | ((lo0 >> 2) & 3))] = pack_h2(v.x, v.y);
    dst[blk + (((lo1 & 3) << 2) | ((lo1 >> 2) & 3))] = pack_h2(v.z, v.w);
}

// gate_up variant: interleave rows (dst row 2f = gate f, 2f+1 = up f)
__global__ void convperm_gu_kernel(const float* __restrict__ src,
                                   unsigned* __restrict__ dst, long n)
{
    long i4 = ((long)blockIdx.x * blockDim.x + threadIdx.x) * 4;
    if (i4 >= n) return;
    long rowd = i4 / HID;
    int  l = (int)(rowd / (2 * FF));
    int  j = (int)(rowd % (2 * FF));
    int  srcj = (j & 1) ? (FF + (j >> 1)) : (j >> 1);
    long si = ((long)l * 2 * FF + srcj) * HID + (i4 % HID);
    float4 v = *(const float4*)(src + si);
    long j0 = i4 >> 1;
    long blk = j0 & ~15L;
    int lo0 = (int)(j0 & 15), lo1 = lo0 + 1;
    dst[blk + (((lo0 & 3) << 2) | ((lo0 >> 2) & 3))] = pack_h2(v.x, v.y);
    dst[blk + (((lo1 & 3) << 2) | ((lo1 >> 2) & 3))] = pack_h2(v.z, v.w);
}

// ---------------- RMSNorm (f32 out, or fp16-permuted out) ----------------
template<bool H16>
__global__ void rmsnorm_kernel(const float* __restrict__ in,
                               const float* __restrict__ w,
                               void* __restrict__ outv, int n)
{
    __shared__ float red[256];
    int row = blockIdx.x;
    const float* x = in + (size_t)row * n;
    float s = 0.f;
    for (int i = threadIdx.x; i < n; i += 256) { float v = x[i]; s += v * v; }
    red[threadIdx.x] = s; __syncthreads();
    for (int st = 128; st > 0; st >>= 1) {
        if (threadIdx.x < st) red[threadIdx.x] += red[threadIdx.x + st];
        __syncthreads();
    }
    float inv = rsqrtf(red[0] / (float)n + EPS);
    if (H16) {
        __half* y = (__half*)outv + (size_t)row * n;
        for (int i = threadIdx.x; i < n; i += 256)
            y[PERMH(i)] = __float2half_rn(w[i] * x[i] * inv);
    } else {
        float* y = (float*)outv + (size_t)row * n;
        for (int i = threadIdx.x; i < n; i += 256)
            y[i] = w[i] * x[i] * inv;
    }
}

// ---------------- fp16 GEMM, batched, K-step 64, 3-stage, 4 warps ----------
// (R14 core: CTA 128x128, 128 thr, warp tile 64x64 — empirically best.)
// A [M,K] fp16 pair-permuted (u32 view), B [N,K] same (TRANSB form).
// Stage: A/B = [2 blk][128 row][16 u32]; 32KB/stage, 3 stages (96KB dyn smem).
// OUTMODE: 0 = store f32, 1 = accumulate f32, 2 = store fp16-permuted,
//          3 = fused silu(gate)*up -> fp16-permuted (gate/up interleaved cols)
// cmode: 0 none; 1 = causal K-limit (K_eff = m0+128); 2 = causal tile skip.
template<int OUTMODE>
__global__ __launch_bounds__(128, 2) void hgemm_kernel(
    const unsigned* __restrict__ A, int lda, long sA,
    const unsigned* __restrict__ B, int ldb, long sB, int gdivB,
    void* __restrict__ Cv, int ldc, long sC,
    int K, const int* __restrict__ maskp, int cmode)
{
    extern __shared__ __align__(16) unsigned smem[];   // 3 * 8192 u32

    int bz = blockIdx.z;
    A += (long)bz * sA;
    B += (long)(bz / gdivB) * sB;
    int m0 = blockIdx.y * 128, n0 = blockIdx.x * 128;

    int mon = (maskp != nullptr) ? *maskp : 1;
    if (cmode == 2 && mon && n0 > m0 + 127) return;
    int Keff = K;
    if (cmode == 1 && mon) { int lim = m0 + 128; Keff = (lim < K) ? lim : K; }

    int tid = threadIdx.x;
    int wid = tid >> 5, lane = tid & 31;
    int wm = (wid >> 1) * 64;
    int wn = (wid & 1) * 64;
    int g = lane >> 2, tig = lane & 3;

    float acc[4][8][4];
#pragma unroll
    for (int mi = 0; mi < 4; mi++)
#pragma unroll
        for (int ni = 0; ni < 8; ni++)
#pragma unroll
            for (int r = 0; r < 4; r++) acc[mi][ni][r] = 0.f;

    int nk = Keff >> 6;   // 64 fp16 = 32 u32 per iteration

#define PREFETCH_H(s, k0u)                                                      \
    {                                                                           \
        unsigned* as = smem + (s) * 8192;                                       \
        unsigned* bs = as + 4096;                                               \
        _Pragma("unroll")                                                       \
        for (int i = 0; i < 8; i++) {                                           \
            int c = tid + i * 128;                                              \
            int r = c >> 3, sub = c & 7;                                        \
            int blk = sub >> 2, cf = (sub & 3) * 4;                             \
            cp_async16(as + blk * 2048 + r * 16 + cf,                           \
                       A + (long)(m0 + r) * lda + (k0u) + blk * 16 + cf);       \
            cp_async16(bs + blk * 2048 + r * 16 + cf,                           \
                       B + (long)(n0 + r) * ldb + (k0u) + blk * 16 + cf);       \
        }                                                                       \
        cp_commit();                                                            \
    }

    PREFETCH_H(0, 0);
    if (nk > 1) PREFETCH_H(1, 32);

    int bufc = 0, bufp = 2;
    for (int it = 0; it < nk; it++) {
        if (it + 1 < nk) cp_wait1(); else cp_wait0();
        __syncthreads();
        if (it + 2 < nk) {
            PREFETCH_H(bufp, (it + 2) * 32);
            bufp = (bufp == 2) ? 0 : bufp + 1;
        }

        const unsigned* as = smem + bufc * 8192;
        const unsigned* bs = as + 4096;
        bufc = (bufc == 2) ? 0 : bufc + 1;

#pragma unroll
        for (int blk = 0; blk < 2; blk++) {
            const unsigned* ab = as + blk * 2048;
            const unsigned* bb = bs + blk * 2048;

            uint4 qb[8], qg[4], qh[4];
#pragma unroll
            for (int ni = 0; ni < 8; ni++)
                qb[ni] = *(const uint4*)&bb[(wn + ni * 8 + g) * 16 + tig * 4];
#pragma unroll
            for (int mi = 0; mi < 4; mi++) {
                int mr = wm + mi * 16 + g;
                qg[mi] = *(const uint4*)&ab[mr * 16 + tig * 4];
                qh[mi] = *(const uint4*)&ab[(mr + 8) * 16 + tig * 4];
            }

            // sweep 0: k = 0..15 of this block
#pragma unroll
            for (int mi = 0; mi < 4; mi++) {
                unsigned a0[4] = {qg[mi].x, qh[mi].x, qg[mi].y, qh[mi].y};
#pragma unroll
                for (int ni = 0; ni < 8; ni++) {
                    unsigned b0[2] = {qb[ni].x, qb[ni].y};
                    mma_f16(acc[mi][ni], a0, b0);
                }
            }
            // sweep 1: k = 16..31 of this block
#pragma unroll
            for (int mi = 0; mi < 4; mi++) {
                unsigned a1[4] = {qg[mi].z, qh[mi].z, qg[mi].w, qh[mi].w};
#pragma unroll
                for (int ni = 0; ni < 8; ni++) {
                    unsigned b1[2] = {qb[ni].z, qb[ni].w};
                    mma_f16(acc[mi][ni], a1, b1);
                }
            }
        }
    }

#pragma unroll
    for (int mi = 0; mi < 4; mi++) {
        int row = m0 + wm + mi * 16 + g;
#pragma unroll
        for (int ni = 0; ni < 8; ni++) {
            int col = n0 + wn + ni * 8 + 2 * tig;
            if (OUTMODE == 2) {
                __half* Ch = (__half*)Cv + (long)bz * sC;
                Ch[(long)row * ldc + PERMH(col)]     = __float2half_rn(acc[mi][ni][0]);
                Ch[(long)row * ldc + PERMH(col + 1)] = __float2half_rn(acc[mi][ni][1]);
                Ch[(long)(row + 8) * ldc + PERMH(col)]     = __float2half_rn(acc[mi][ni][2]);
                Ch[(long)(row + 8) * ldc + PERMH(col + 1)] = __float2half_rn(acc[mi][ni][3]);
            } else if (OUTMODE == 3) {
                __half* Ch = (__half*)Cv;
                int f0 = col >> 1;        // col even: (gate, up) pair
                float g0 = acc[mi][ni][0], u0 = acc[mi][ni][1];
                float g1 = acc[mi][ni][2], u1 = acc[mi][ni][3];
                Ch[(long)row * ldc + PERMH(f0)] =
                    __float2half_rn((g0 / (1.f + expf(-g0))) * u0);
                Ch[(long)(row + 8) * ldc + PERMH(f0)] =
                    __float2half_rn((g1 / (1.f + expf(-g1))) * u1);
            } else {
                float* C = (float*)Cv + (long)bz * sC;
                float2* p0 = (float2*)(C + (long)row * ldc + col);
                float2* p1 = (float2*)(C + (long)(row + 8) * ldc + col);
                if (OUTMODE == 1) {
                    float2 o0 = *p0, o1 = *p1;
                    o0.x += acc[mi][ni][0]; o0.y += acc[mi][ni][1];
                    o1.x += acc[mi][ni][2]; o1.y += acc[mi][ni][3];
                    *p0 = o0; *p1 = o1;
                } else {
                    *p0 = make_float2(acc[mi][ni][0], acc[mi][ni][1]);
                    *p1 = make_float2(acc[mi][ni][2], acc[mi][ni][3]);
                }
            }
        }
    }
}
#undef PREFETCH_H

#define HSMEM (3 * 8192 * 4)

// ---------------- split qkv + rope + scale ----------------
__global__ void rope_split_kernel(const float* __restrict__ qkv,
                                  const float* __restrict__ cosE,
                                  const float* __restrict__ sinE,
                                  __half* __restrict__ q_h,
                                  float* __restrict__ keys,     // [KV][D][S]
                                  float* __restrict__ vals,     // [KV][S][D]
                                  __half* __restrict__ kT_h,
                                  __half* __restrict__ vT_h)
{
    long idx = (long)blockIdx.x * blockDim.x + threadIdx.x;
    if (idx >= (long)SS * QKV_O) return;
    int s = (int)(idx / QKV_O);
    int c = (int)(idx % QKV_O);
    float v = qkv[idx];
    float scale = SCALE_C;
    if (c < QP) {
        int hh = c / DD, d = c % DD;
        float val = v * scale;
        if (d < ROT) {
            int pd = (d < HALF) ? d + HALF : d - HALF;
            float partner = qkv[(long)s * QKV_O + hh * DD + pd] * scale;
            float r = (d < HALF) ? -partner : partner;
            val = val * cosE[s * ROT + d] + r * sinE[s * ROT + d];
        }
        q_h[((size_t)hh * SS + s) * DD + PERMH(d)] = __float2half_rn(val);
    } else if (c < QP + KP) {
        int kc = c - QP;
        int kv = kc / DD, d = kc % DD;
        float val = v * scale;
        if (d < ROT) {
            int pd = (d < HALF) ? d + HALF : d - HALF;
            float partner = qkv[(long)s * QKV_O + QP + kv * DD + pd] * scale;
            float r = (d < HALF) ? -partner : partner;
            val = val * cosE[s * ROT + d] + r * sinE[s * ROT + d];
        }
        keys[((size_t)kv * DD + d) * SS + s] = val;
        kT_h[((size_t)kv * SS + s) * DD + PERMH(d)] = __float2half_rn(val);
    } else {
        int vc = c - QP - KP;
        int kv = vc / DD, d = vc % DD;
        vals[((size_t)kv * SS + s) * DD + d] = v;
        vT_h[((size_t)kv * DD + d) * SS + PERMH(s)] = __float2half_rn(v);
    }
}

// ---------------- softmax: causal-aware; writes fp16-permuted probs ---------
__global__ void softmax_kernel(const float* __restrict__ sc,
                               __half* __restrict__ pb,
                               const int* __restrict__ maskf)
{
    __shared__ float red[256];
    int s = blockIdx.x, h = blockIdx.y;
    const float* row = sc + ((size_t)h * SS + s) * SS;
    __half* prow = pb + ((size_t)h * SS + s) * SS;
    int mflag = maskf ? *maskf : 1;
    bool cz = (mflag != 0);
    int tid = threadIdx.x;
    float vals[4]; bool act[4];
    float lmax = -3.4e38f;
#pragma unroll
    for (int i = 0; i < 4; i++) {
        int t = tid + i * 256;
        bool a = (!cz) || (t <= s);
        act[i] = a;
        float x = a ? row[t] : -3.4e38f;
        vals[i] = x;
        lmax = fmaxf(lmax, x);
    }
    red[tid] = lmax; __syncthreads();
    for (int st = 128; st > 0; st >>= 1) {
        if (tid < st) red[tid] = fmaxf(red[tid], red[tid + st]);
        __syncthreads();
    }
    float mx = red[0]; __syncthreads();
    float lsum = 0.f;
#pragma unroll
    for (int i = 0; i < 4; i++) {
        vals[i] = act[i] ? expf(vals[i] - mx) : 0.f;
        lsum += vals[i];
    }
    red[tid] = lsum; __syncthreads();
    for (int st = 128; st > 0; st >>= 1) {
        if (tid < st) red[tid] += red[tid + st];
        __syncthreads();
    }
    float inv = 1.f / red[0];
#pragma unroll
    for (int i = 0; i < 4; i++) {
        int t = tid + i * 256;
        prow[PERMH(t)] = __float2half_rn(vals[i] * inv);
    }
}

// ---------------- lm_head ----------------
__global__ void lmhead_kernel(const float* __restrict__ hl,
                              const float* __restrict__ w,
                              float* __restrict__ logits)
{
    int gtid = blockIdx.x * blockDim.x + threadIdx.x;
    int warp = gtid >> 5, lane = gtid & 31;
    if (warp >= VV) return;
    const float* wr = w + (size_t)warp * HID;
    float s = 0.f;
    for (int k = lane; k < HID; k += 32) s = fmaf(hl[k], wr[k], s);
#pragma unroll
    for (int off = 16; off > 0; off >>= 1)
        s += __shfl_down_sync(0xffffffffu, s, off);
    if (lane == 0) logits[warp] = s;
}

// ---------------- argmax + scalar outputs ----------------
__global__ void argmax_kernel(const float* __restrict__ lg, float* __restrict__ outf)
{
    __shared__ float bv[1024];
    __shared__ int   bi[1024];
    int tid = threadIdx.x;
    float best = -3.4e38f; int bidx = 0;
    for (int t = tid; t < VV; t += 1024) {
        float v = lg[t];
        if (v > best) { best = v; bidx = t; }
    }
    bv[tid] = best; bi[tid] = bidx; __syncthreads();
    for (int st = 512; st > 0; st >>= 1) {
        if (tid < st) {
            if (bv[tid + st] > bv[tid] ||
                (bv[tid + st] == bv[tid] && bi[tid + st] < bi[tid])) {
                bv[tid] = bv[tid + st]; bi[tid] = bi[tid + st];
            }
        }
        __syncthreads();
    }
    if (tid == 0) {
        outf[OUT_KVLEN] = (float)SS;
        outf[OUT_TOKEN] = (float)bi[0];
    }
}

// ---------------- launch ----------------
extern "C" void kernel_launch(void* const* d_in, const int* in_sizes, int n_in,
                              void* d_out, int out_size)
{
    int i_ids = -1, i_mask = -1, i_eq = -1, i_lm = -1, i_esc = -1, i_ez = -1;
    int i_l1 = -1, i_l2 = -1, i_qkv = -1, i_ow = -1, i_gu = -1, i_dw = -1;
    int i_nw = -1, i_cos = -1, i_sin = -1;
    for (int i = 0; i < n_in; i++) {
        switch (in_sizes[i]) {
            case 1024:      i_ids = i; break;
            case 1:         i_mask = i; break;
            case 98304000:  if (i_eq < 0) i_eq = i; else i_lm = i; break;
            case 32000:     if (i_esc < 0) i_esc = i; else i_ez = i; break;
            case 6144:      if (i_l1 < 0) i_l1 = i; else i_l2 = i; break;
            case 31457280:  i_qkv = i; break;
            case 18874368:  i_ow = i; break;
            case 100663296: i_gu = i; break;
            case 50331648:  i_dw = i; break;
            case 3072:      i_nw = i; break;
            case 98304:     if (i_cos < 0) i_cos = i; else i_sin = i; break;
            default: break;
        }
    }
    const int*   ids    = (const int*)d_in[i_ids];
    const int*   maskf  = (i_mask >= 0) ? (const int*)d_in[i_mask] : nullptr;
    const void*  eq     = d_in[i_eq];
    const float* escale = (const float*)d_in[i_esc];
    const float* ezero  = (const float*)d_in[i_ez];
    const float* ln1    = (const float*)d_in[i_l1];
    const float* qkvw   = (const float*)d_in[i_qkv];
    const float* ow     = (const float*)d_in[i_ow];
    const float* ln2    = (const float*)d_in[i_l2];
    const float* guw    = (const float*)d_in[i_gu];
    const float* dw     = (const float*)d_in[i_dw];
    const float* normw  = (const float*)d_in[i_nw];
    const float* lmw    = (const float*)d_in[i_lm];
    const float* cosE   = (const float*)d_in[i_cos];
    const float* sinE   = (const float*)d_in[i_sin];
    float* out = (float*)d_out;

    float* scr = nullptr;
    cudaGetSymbolAddress((void**)&scr, g_scratch);
    float*    hbuf   = scr + OFF_H;
    __half*   hn_h   = (__half*)(scr + OFF_HN);
    float*    qkv    = scr + OFF_QKV;
    __half*   q_h    = (__half*)(scr + OFF_Q);
    float*    scores = scr + OFF_SC;
    __half*   probs  = (__half*)(scr + OFF_PB);
    __half*   ao_h   = (__half*)(scr + OFF_AO);
    __half*   act_h  = (__half*)(scr + OFF_ACT);
    __half*   kT_h   = (__half*)(scr + OFF_KT);
    __half*   vT_h   = (__half*)(scr + OFF_VT);
    float*    hl     = scr + OFF_HL;
    float*    logits = scr + OFF_LG;
    int*      flag   = (int*)(scr + OFF_FLAG);
    unsigned* wqkv_c = (unsigned*)(scr + OFF_WQKV);
    unsigned* wo_c   = (unsigned*)(scr + OFF_WO);
    unsigned* wgu_c  = (unsigned*)(scr + OFF_WGU);
    unsigned* wdw_c  = (unsigned*)(scr + OFF_WDW);
    float*    keys   = out + OUT_KEYS;
    float*    valsb  = out + OUT_VALS;

    cudaFuncSetAttribute(hgemm_kernel<0>,
                         cudaFuncAttributeMaxDynamicSharedMemorySize, HSMEM);
    cudaFuncSetAttribute(hgemm_kernel<1>,
                         cudaFuncAttributeMaxDynamicSharedMemorySize, HSMEM);
    cudaFuncSetAttribute(hgemm_kernel<2>,
                         cudaFuncAttributeMaxDynamicSharedMemorySize, HSMEM);
    cudaFuncSetAttribute(hgemm_kernel<3>,
                         cudaFuncAttributeMaxDynamicSharedMemorySize, HSMEM);

    // ---- one-time-per-launch weight conversion (fp16 + pair-permute) ----
    {
        long n;
        n = (long)LL * QKV_O * HID;
        convperm_h_kernel<<<(unsigned)((n / 4 + 255) / 256), 256>>>(qkvw, wqkv_c, n);
        n = (long)LL * HID * QP;
        convperm_h_kernel<<<(unsigned)((n / 4 + 255) / 256), 256>>>(ow, wo_c, n);
        n = (long)LL * 2 * FF * HID;
        convperm_gu_kernel<<<(unsigned)((n / 4 + 255) / 256), 256>>>(guw, wgu_c, n);
        n = (long)LL * HID * FF;
        convperm_h_kernel<<<(unsigned)((n / 4 + 255) / 256), 256>>>(dw, wdw_c, n);
    }

    detect_dtype_kernel<<<1, 1>>>((const unsigned int*)eq, flag);
    embed_kernel<<<SS, 256>>>(ids, eq, escale, ezero, flag, hbuf);

    for (int l = 0; l < LL; l++) {
        float* lkeys = keys  + (size_t)l * KVH * DD * SS;
        float* lvals = valsb + (size_t)l * KVH * SS * DD;

        // hn = rms(h, ln1)  (fp16-permuted)
        rmsnorm_kernel<true><<<SS, 256>>>(hbuf, ln1 + (size_t)l * HID, hn_h, HID);
        // qkv = hn @ qkv_w^T
        hgemm_kernel<0><<<dim3(QKV_O / 128, SS / 128, 1), 128, HSMEM>>>(
            (const unsigned*)hn_h, HID / 2, 0,
            wqkv_c + (size_t)l * QKV_O * HID / 2, HID / 2, 0, 1,
            qkv, QKV_O, 0, HID, nullptr, 0);
        // rope + split (f32 caches + fp16 attention operands)
        rope_split_kernel<<<(SS * QKV_O) / 256, 256>>>(
            qkv, cosE, sinE, q_h, lkeys, lvals, kT_h, vT_h);
        // scores = q @ k^T (causal tile skip)
        hgemm_kernel<0><<<dim3(SS / 128, SS / 128, HH), 128, HSMEM>>>(
            (const unsigned*)q_h, DD / 2, (long)SS * DD / 2,
            (const unsigned*)kT_h, DD / 2, (long)SS * DD / 2, GG,
            scores, SS, (long)SS * SS, DD, maskf, 2);
        // softmax -> fp16-permuted probs (causal-aware)
        softmax_kernel<<<dim3(SS, HH), 256>>>(scores, probs, maskf);
        // ao = P @ v  (causal K-limit) -> fp16-permuted
        hgemm_kernel<2><<<dim3(DD / 128, SS / 128, HH), 128, HSMEM>>>(
            (const unsigned*)probs, SS / 2, (long)SS * SS / 2,
            (const unsigned*)vT_h, SS / 2, (long)DD * SS / 2, GG,
            ao_h, HID, (long)DD, SS, maskf, 1);
        // h += ao @ o_w^T
        hgemm_kernel<1><<<dim3(HID / 128, SS / 128, 1), 128, HSMEM>>>(
            (const unsigned*)ao_h, QP / 2, 0,
            wo_c + (size_t)l * HID * QP / 2, QP / 2, 0, 1,
            hbuf, HID, 0, QP, nullptr, 0);
        // hn = rms(h, ln2) (fp16-permuted)
        rmsnorm_kernel<true><<<SS, 256>>>(hbuf, ln2 + (size_t)l * HID, hn_h, HID);
        // act = silu(gate)*up fused into gate_up GEMM (interleaved weights)
        hgemm_kernel<3><<<dim3(2 * FF / 128, SS / 128, 1), 128, HSMEM>>>(
            (const unsigned*)hn_h, HID / 2, 0,
            wgu_c + (size_t)l * 2 * FF * HID / 2, HID / 2, 0, 1,
            act_h, FF, 0, HID, nullptr, 0);
        // h += act @ down_w^T
        hgemm_kernel<1><<<dim3(HID / 128, SS / 128, 1), 128, HSMEM>>>(
            (const unsigned*)act_h, FF / 2, 0,
            wdw_c + (size_t)l * HID * FF / 2, FF / 2, 0, 1,
            hbuf, HID, 0, FF, nullptr, 0);
    }

    rmsnorm_kernel<false><<<1, 256>>>(hbuf + (size_t)(SS - 1) * HID, normw, hl, HID);
    lmhead_kernel<<<(VV * 32) / 256, 256>>>(hl, lmw, logits);
    argmax_kernel<<<1, 1024>>>(logits, (float*)d_out);
}